// round 1
// baseline (speedup 1.0000x reference)
#include <cuda_runtime.h>

#define NN   50000
#define EE   600000
#define FEAT 11
#define DD   128
#define BBATCH 500
#define MAXA 100
#define NLAYERS 5
#define DENSE (BBATCH*MAXA*DD)   /* 6,400,000 */

// -------- scratch (static device globals; no runtime allocation) --------
__device__ float g_x[NN*DD];        // 25.6 MB ping
__device__ float g_agg[NN*DD];      // 25.6 MB pong
__device__ float g_dinv[NN];
__device__ float g_self[NN];
__device__ int   g_deg[NN];
__device__ int   g_rowstart[NN+1];
__device__ int   g_cursor[NN];
__device__ int   g_csr_src[EE];
__device__ float g_csr_w[EE];
__device__ int   g_counts[BBATCH];
__device__ int   g_ptr[BBATCH];

// ---------------- graph preprocessing ----------------
__global__ void k_zero()
{
    int i = blockIdx.x * blockDim.x + threadIdx.x;
    if (i < NN) g_deg[i] = 0;
    if (i < BBATCH) g_counts[i] = 0;
}

__global__ void k_hist(const int* __restrict__ col, const int* __restrict__ batch)
{
    int i = blockIdx.x * blockDim.x + threadIdx.x;
    if (i < EE) atomicAdd(&g_deg[col[i]], 1);
    if (i < NN) atomicAdd(&g_counts[batch[i]], 1);
}

__global__ void k_dinv()
{
    int i = blockIdx.x * blockDim.x + threadIdx.x;
    if (i >= NN) return;
    float d  = (float)g_deg[i] + 2.0f;
    float di = rsqrtf(d);
    g_dinv[i] = di;
    g_self[i] = 2.0f * di * di;
}

// single-block scan: g_deg -> g_rowstart (inclusive shifted) + g_cursor (exclusive),
// plus serial exclusive scan of per-graph counts -> g_ptr.
__global__ void k_scan()
{
    __shared__ int warp_sums[32];
    __shared__ int s_carry;
    int tid  = threadIdx.x;
    int lane = tid & 31;
    int wid  = tid >> 5;
    if (tid == 0) { s_carry = 0; g_rowstart[0] = 0; }
    __syncthreads();

    for (int base = 0; base < NN; base += 1024) {
        int i  = base + tid;
        int v0 = (i < NN) ? g_deg[i] : 0;
        int v  = v0;
        #pragma unroll
        for (int off = 1; off < 32; off <<= 1) {
            int t = __shfl_up_sync(0xffffffffu, v, off);
            if (lane >= off) v += t;
        }
        if (lane == 31) warp_sums[wid] = v;
        __syncthreads();
        if (wid == 0) {
            int s = warp_sums[lane];
            #pragma unroll
            for (int off = 1; off < 32; off <<= 1) {
                int t = __shfl_up_sync(0xffffffffu, s, off);
                if (lane >= off) s += t;
            }
            warp_sums[lane] = s;
        }
        __syncthreads();
        int prefix = s_carry + (wid ? warp_sums[wid-1] : 0);
        int incl   = prefix + v;
        if (i < NN) {
            g_rowstart[i+1] = incl;
            g_cursor[i]     = incl - v0;
        }
        __syncthreads();
        if (tid == 0) s_carry += warp_sums[31];
        __syncthreads();
    }

    if (tid == 0) {
        int acc = 0;
        for (int b = 0; b < BBATCH; b++) { g_ptr[b] = acc; acc += g_counts[b]; }
    }
}

__global__ void k_csr(const int* __restrict__ conn)
{
    int e = blockIdx.x * blockDim.x + threadIdx.x;
    if (e >= EE) return;
    int r = conn[e];
    int c = conn[EE + e];
    int slot = atomicAdd(&g_cursor[c], 1);
    g_csr_src[slot] = r;
    g_csr_w[slot]   = g_dinv[r] * g_dinv[c];
}

// ---------------- log-expansion: x0 = log(atoms+1) @ W_exp + b_exp ----------------
__global__ void k_expand(const float* __restrict__ atoms,
                         const float* __restrict__ Wexp,
                         const float* __restrict__ bexp)
{
    __shared__ float sW[FEAT*DD];
    __shared__ float sb[DD];
    __shared__ float la[FEAT];
    int tid = threadIdx.x;                    // 128 threads, one per output dim
    for (int i = tid; i < FEAT*DD; i += DD) sW[i] = Wexp[i];
    sb[tid] = bexp[tid];
    for (int n = blockIdx.x; n < NN; n += gridDim.x) {
        __syncthreads();
        if (tid < FEAT) la[tid] = logf(atoms[n*FEAT + tid] + 1.0f);
        __syncthreads();
        float acc = sb[tid];
        #pragma unroll
        for (int f = 0; f < FEAT; f++) acc = fmaf(la[f], sW[f*DD + tid], acc);
        g_x[n*DD + tid] = acc;
    }
}

// ---------------- per-layer aggregation: agg = Â x (CSR, warp per node) ----------------
__global__ void k_agg(const float* __restrict__ x, float* __restrict__ agg)
{
    int w = (blockIdx.x * blockDim.x + threadIdx.x) >> 5;
    if (w >= NN) return;
    int lane = threadIdx.x & 31;
    const float4* xr = reinterpret_cast<const float4*>(x);

    float4 a  = xr[w*32 + lane];
    float  sn = g_self[w];
    float4 acc = make_float4(a.x*sn, a.y*sn, a.z*sn, a.w*sn);

    int s = g_rowstart[w];
    int e = g_rowstart[w+1];
    for (int j = s; j < e; j++) {
        int   src = g_csr_src[j];
        float wt  = g_csr_w[j];
        float4 u  = xr[src*32 + lane];
        acc.x = fmaf(u.x, wt, acc.x);
        acc.y = fmaf(u.y, wt, acc.y);
        acc.z = fmaf(u.z, wt, acc.z);
        acc.w = fmaf(u.w, wt, acc.w);
    }
    reinterpret_cast<float4*>(agg)[w*32 + lane] = acc;
}

// ---------------- GEMM + bias + relu: out = relu(A @ W + b) ----------------
// A: [NN,128], W: [128,128], 64-row tiles, 256 threads, 4x8 register blocking.
__global__ __launch_bounds__(256)
void k_gemm(const float* __restrict__ A, const float* __restrict__ W,
            const float* __restrict__ bias, float* __restrict__ out)
{
    __shared__ __align__(16) float sA[64][33];
    __shared__ __align__(16) float sW[32][DD];

    int tid = threadIdx.x;
    int tr  = tid >> 4;        // 0..15 -> rows tr*4..tr*4+3
    int tc  = tid & 15;        // 0..15 -> cols tc*8..tc*8+7
    int rowBase = blockIdx.x * 64;

    float acc[4][8];
    #pragma unroll
    for (int r = 0; r < 4; r++)
        #pragma unroll
        for (int c = 0; c < 8; c++) acc[r][c] = 0.0f;

    for (int kt = 0; kt < DD; kt += 32) {
        // stage A tile 64x32 (512 float4, 2 per thread)
        #pragma unroll
        for (int it = 0; it < 2; it++) {
            int li = tid + it*256;
            int r  = li >> 3;
            int c4 = li & 7;
            int grow = rowBase + r;
            float4 v = make_float4(0.f, 0.f, 0.f, 0.f);
            if (grow < NN)
                v = *reinterpret_cast<const float4*>(A + grow*DD + kt + c4*4);
            sA[r][c4*4+0] = v.x; sA[r][c4*4+1] = v.y;
            sA[r][c4*4+2] = v.z; sA[r][c4*4+3] = v.w;
        }
        // stage W tile 32x128 (1024 float4, 4 per thread)
        #pragma unroll
        for (int it = 0; it < 4; it++) {
            int li = tid + it*256;
            int r  = li >> 5;
            int c4 = li & 31;
            float4 v = *reinterpret_cast<const float4*>(W + (kt + r)*DD + c4*4);
            *reinterpret_cast<float4*>(&sW[r][c4*4]) = v;
        }
        __syncthreads();

        #pragma unroll
        for (int k = 0; k < 32; k++) {
            float av[4];
            #pragma unroll
            for (int r = 0; r < 4; r++) av[r] = sA[tr*4 + r][k];
            float4 w0 = *reinterpret_cast<const float4*>(&sW[k][tc*8]);
            float4 w1 = *reinterpret_cast<const float4*>(&sW[k][tc*8 + 4]);
            float wv[8] = {w0.x, w0.y, w0.z, w0.w, w1.x, w1.y, w1.z, w1.w};
            #pragma unroll
            for (int r = 0; r < 4; r++)
                #pragma unroll
                for (int c = 0; c < 8; c++)
                    acc[r][c] = fmaf(av[r], wv[c], acc[r][c]);
        }
        __syncthreads();
    }

    float bv[8];
    #pragma unroll
    for (int c = 0; c < 8; c++) bv[c] = bias[tc*8 + c];
    #pragma unroll
    for (int r = 0; r < 4; r++) {
        int grow = rowBase + tr*4 + r;
        if (grow < NN) {
            float4 o0, o1;
            o0.x = fmaxf(acc[r][0] + bv[0], 0.f);
            o0.y = fmaxf(acc[r][1] + bv[1], 0.f);
            o0.z = fmaxf(acc[r][2] + bv[2], 0.f);
            o0.w = fmaxf(acc[r][3] + bv[3], 0.f);
            o1.x = fmaxf(acc[r][4] + bv[4], 0.f);
            o1.y = fmaxf(acc[r][5] + bv[5], 0.f);
            o1.z = fmaxf(acc[r][6] + bv[6], 0.f);
            o1.w = fmaxf(acc[r][7] + bv[7], 0.f);
            *reinterpret_cast<float4*>(out + grow*DD + tc*8)     = o0;
            *reinterpret_cast<float4*>(out + grow*DD + tc*8 + 4) = o1;
        }
    }
}

// ---------------- output: zero, then scatter dense rows + mask ----------------
__global__ void k_zero_out(float* __restrict__ out, int n)
{
    int i = blockIdx.x * blockDim.x + threadIdx.x;
    if (i < n) out[i] = 0.0f;
}

__global__ void k_out(const int* __restrict__ batch, float* __restrict__ out, int out_size)
{
    int w = (blockIdx.x * blockDim.x + threadIdx.x) >> 5;
    if (w >= NN) return;
    int lane = threadIdx.x & 31;
    int b    = batch[w];
    int idx  = b*MAXA + (w - g_ptr[b]);
    float4 v = reinterpret_cast<const float4*>(g_x)[w*32 + lane];
    reinterpret_cast<float4*>(out)[idx*32 + lane] = v;
    if (lane == 0 && out_size >= DENSE + BBATCH*MAXA)
        out[DENSE + idx] = 1.0f;   // mask True
}

// ---------------- launch ----------------
extern "C" void kernel_launch(void* const* d_in, const int* in_sizes, int n_in,
                              void* d_out, int out_size)
{
    const float* atoms = (const float*)d_in[0];
    const int*   conn  = (const int*)d_in[1];
    const int*   batch = (const int*)d_in[2];
    const float* W_exp = (const float*)d_in[3];
    const float* b_exp = (const float*)d_in[4];
    const float* Ws    = (const float*)d_in[5];
    const float* bs    = (const float*)d_in[6];
    float* out = (float*)d_out;

    float *px, *pagg;
    cudaGetSymbolAddress((void**)&px,   g_x);
    cudaGetSymbolAddress((void**)&pagg, g_agg);

    k_zero<<<(NN + 255)/256, 256>>>();
    k_hist<<<(EE + 255)/256, 256>>>(conn + EE, batch);
    k_dinv<<<(NN + 255)/256, 256>>>();
    k_scan<<<1, 1024>>>();
    k_csr<<<(EE + 255)/256, 256>>>(conn);
    k_expand<<<4096, DD>>>(atoms, W_exp, b_exp);

    int aggBlocks  = (NN*32 + 255)/256;
    int gemmBlocks = (NN + 63)/64;
    for (int l = 0; l < NLAYERS; l++) {
        k_agg<<<aggBlocks, 256>>>(px, pagg);
        k_gemm<<<gemmBlocks, 256>>>(pagg, Ws + l*DD*DD, bs + l*DD, px);
    }

    k_zero_out<<<(out_size + 255)/256, 256>>>(out, out_size);
    k_out<<<aggBlocks, 256>>>(batch, out, out_size);
}

// round 2
// speedup vs baseline: 1.1005x; 1.1005x over previous
#include <cuda_runtime.h>

#define NN   50000
#define EE   600000
#define FEAT 11
#define DD   128
#define BBATCH 500
#define MAXA 100
#define NLAYERS 5
#define DENSE (BBATCH*MAXA*DD)   /* 6,400,000 */

#define SCAN_BS   1024
#define SCAN_NB   ((NN + SCAN_BS - 1) / SCAN_BS)   /* 49 */

// -------- scratch (static device globals; no runtime allocation) --------
__device__ float g_x[NN*DD];        // 25.6 MB ping
__device__ float g_agg[NN*DD];      // 25.6 MB pong
__device__ float g_dinv[NN];
__device__ float g_self[NN];
__device__ int   g_deg[NN];
__device__ int   g_rowstart[NN+1];
__device__ int   g_cursor[NN];
__device__ int   g_csr_src[EE];
__device__ float g_csr_w[EE];
__device__ int   g_counts[BBATCH];
__device__ int   g_ptr[BBATCH];
__device__ int   g_bsum[SCAN_NB];
__device__ int   g_boff[SCAN_NB];

// ---------------- graph preprocessing ----------------
__global__ void k_zero()
{
    int i = blockIdx.x * blockDim.x + threadIdx.x;
    if (i < NN) g_deg[i] = 0;
    if (i < BBATCH) g_counts[i] = 0;
}

__global__ void k_hist(const int* __restrict__ col, const int* __restrict__ batch)
{
    int i = blockIdx.x * blockDim.x + threadIdx.x;
    if (i < EE) atomicAdd(&g_deg[col[i]], 1);
    if (i < NN) atomicAdd(&g_counts[batch[i]], 1);
}

__global__ void k_dinv()
{
    int i = blockIdx.x * blockDim.x + threadIdx.x;
    if (i >= NN) return;
    float d  = (float)g_deg[i] + 2.0f;
    float di = rsqrtf(d);
    g_dinv[i] = di;
    g_self[i] = 2.0f * di * di;
}

// ---- scan phase 1: per-block inclusive scan of deg; local results + block sums ----
__global__ __launch_bounds__(SCAN_BS)
void k_scan1()
{
    __shared__ int warp_sums[32];
    int tid  = threadIdx.x;
    int lane = tid & 31;
    int wid  = tid >> 5;
    int i    = blockIdx.x * SCAN_BS + tid;

    int v0 = (i < NN) ? g_deg[i] : 0;
    int v  = v0;
    #pragma unroll
    for (int off = 1; off < 32; off <<= 1) {
        int t = __shfl_up_sync(0xffffffffu, v, off);
        if (lane >= off) v += t;
    }
    if (lane == 31) warp_sums[wid] = v;
    __syncthreads();
    if (wid == 0) {
        int s = warp_sums[lane];
        #pragma unroll
        for (int off = 1; off < 32; off <<= 1) {
            int t = __shfl_up_sync(0xffffffffu, s, off);
            if (lane >= off) s += t;
        }
        warp_sums[lane] = s;
    }
    __syncthreads();
    int incl = v + (wid ? warp_sums[wid-1] : 0);
    if (i < NN) {
        g_rowstart[i+1] = incl;      // block-local, offset added in phase 3
        g_cursor[i]     = incl - v0;
    }
    if (tid == SCAN_BS - 1) g_bsum[blockIdx.x] = incl;
}

// ---- scan phase 2 (one block, 512 thr): exclusive scan of block sums AND counts->ptr ----
__global__ __launch_bounds__(512)
void k_scan2()
{
    __shared__ int sb[64];
    __shared__ int warp_sums[16];
    int tid  = threadIdx.x;
    int lane = tid & 31;
    int wid  = tid >> 5;

    // part A: Hillis-Steele over 64 slots for the 49 block sums
    if (tid < 64) sb[tid] = (tid < SCAN_NB) ? g_bsum[tid] : 0;
    __syncthreads();
    #pragma unroll
    for (int off = 1; off < 64; off <<= 1) {
        int t = 0;
        if (tid < 64 && tid >= off) t = sb[tid - off];
        __syncthreads();
        if (tid < 64) sb[tid] += t;
        __syncthreads();
    }
    if (tid < SCAN_NB) g_boff[tid] = (tid == 0) ? 0 : sb[tid - 1];
    if (tid == 0) g_rowstart[0] = 0;

    // part B: exclusive scan of counts[500] -> ptr (512 threads, 1 elem each)
    int c = (tid < BBATCH) ? g_counts[tid] : 0;
    int v = c;
    #pragma unroll
    for (int off = 1; off < 32; off <<= 1) {
        int t = __shfl_up_sync(0xffffffffu, v, off);
        if (lane >= off) v += t;
    }
    if (lane == 31) warp_sums[wid] = v;
    __syncthreads();
    if (wid == 0 && lane < 16) {
        int s = warp_sums[lane];
        #pragma unroll
        for (int off = 1; off < 16; off <<= 1) {
            int t = __shfl_up_sync(0xffffu, s, off);
            if (lane >= off) s += t;
        }
        warp_sums[lane] = s;
    }
    __syncthreads();
    int incl = v + (wid ? warp_sums[wid-1] : 0);
    if (tid < BBATCH) g_ptr[tid] = incl - c;   // exclusive
}

// ---- scan phase 3: add block offsets ----
__global__ __launch_bounds__(SCAN_BS)
void k_scan3()
{
    int i = blockIdx.x * SCAN_BS + threadIdx.x;
    if (i >= NN) return;
    int off = g_boff[blockIdx.x];
    g_rowstart[i+1] += off;
    g_cursor[i]     += off;
}

__global__ void k_csr(const int* __restrict__ conn)
{
    int e = blockIdx.x * blockDim.x + threadIdx.x;
    if (e >= EE) return;
    int r = conn[e];
    int c = conn[EE + e];
    int slot = atomicAdd(&g_cursor[c], 1);
    g_csr_src[slot] = r;
    g_csr_w[slot]   = g_dinv[r] * g_dinv[c];
}

// ---------------- log-expansion: x0 = log(atoms+1) @ W_exp + b_exp ----------------
__global__ void k_expand(const float* __restrict__ atoms,
                         const float* __restrict__ Wexp,
                         const float* __restrict__ bexp)
{
    __shared__ float sW[FEAT*DD];
    __shared__ float sb[DD];
    __shared__ float la[FEAT];
    int tid = threadIdx.x;                    // 128 threads, one per output dim
    for (int i = tid; i < FEAT*DD; i += DD) sW[i] = Wexp[i];
    sb[tid] = bexp[tid];
    for (int n = blockIdx.x; n < NN; n += gridDim.x) {
        __syncthreads();
        if (tid < FEAT) la[tid] = logf(atoms[n*FEAT + tid] + 1.0f);
        __syncthreads();
        float acc = sb[tid];
        #pragma unroll
        for (int f = 0; f < FEAT; f++) acc = fmaf(la[f], sW[f*DD + tid], acc);
        g_x[n*DD + tid] = acc;
    }
}

// ---------------- per-layer aggregation: agg = Â x (CSR, warp per node) ----------------
// 4x unrolled: batch the index/weight loads, then 4 independent float4 gathers (MLP=4).
__global__ void k_agg(const float* __restrict__ x, float* __restrict__ agg)
{
    int w = (blockIdx.x * blockDim.x + threadIdx.x) >> 5;
    if (w >= NN) return;
    int lane = threadIdx.x & 31;
    const float4* xr = reinterpret_cast<const float4*>(x);

    float4 a  = xr[w*32 + lane];
    float  sn = g_self[w];
    float4 acc = make_float4(a.x*sn, a.y*sn, a.z*sn, a.w*sn);

    int s = g_rowstart[w];
    int e = g_rowstart[w+1];
    int j = s;
    for (; j + 4 <= e; j += 4) {
        int   s0 = g_csr_src[j],   s1 = g_csr_src[j+1];
        int   s2 = g_csr_src[j+2], s3 = g_csr_src[j+3];
        float w0 = g_csr_w[j],     w1 = g_csr_w[j+1];
        float w2 = g_csr_w[j+2],   w3 = g_csr_w[j+3];
        float4 u0 = xr[s0*32 + lane];
        float4 u1 = xr[s1*32 + lane];
        float4 u2 = xr[s2*32 + lane];
        float4 u3 = xr[s3*32 + lane];
        acc.x = fmaf(u0.x, w0, acc.x); acc.y = fmaf(u0.y, w0, acc.y);
        acc.z = fmaf(u0.z, w0, acc.z); acc.w = fmaf(u0.w, w0, acc.w);
        acc.x = fmaf(u1.x, w1, acc.x); acc.y = fmaf(u1.y, w1, acc.y);
        acc.z = fmaf(u1.z, w1, acc.z); acc.w = fmaf(u1.w, w1, acc.w);
        acc.x = fmaf(u2.x, w2, acc.x); acc.y = fmaf(u2.y, w2, acc.y);
        acc.z = fmaf(u2.z, w2, acc.z); acc.w = fmaf(u2.w, w2, acc.w);
        acc.x = fmaf(u3.x, w3, acc.x); acc.y = fmaf(u3.y, w3, acc.y);
        acc.z = fmaf(u3.z, w3, acc.z); acc.w = fmaf(u3.w, w3, acc.w);
    }
    for (; j < e; j++) {
        int   src = g_csr_src[j];
        float wt  = g_csr_w[j];
        float4 u  = xr[src*32 + lane];
        acc.x = fmaf(u.x, wt, acc.x);
        acc.y = fmaf(u.y, wt, acc.y);
        acc.z = fmaf(u.z, wt, acc.z);
        acc.w = fmaf(u.w, wt, acc.w);
    }
    reinterpret_cast<float4*>(agg)[w*32 + lane] = acc;
}

// ---------------- GEMM + bias + relu: out = relu(A @ W + b) ----------------
// A: [NN,128], W: [128,128], 64-row tiles, 256 threads, 4x8 register blocking.
__global__ __launch_bounds__(256)
void k_gemm(const float* __restrict__ A, const float* __restrict__ W,
            const float* __restrict__ bias, float* __restrict__ out)
{
    __shared__ __align__(16) float sA[64][33];
    __shared__ __align__(16) float sW[32][DD];

    int tid = threadIdx.x;
    int tr  = tid >> 4;        // 0..15 -> rows tr*4..tr*4+3
    int tc  = tid & 15;        // 0..15 -> cols tc*8..tc*8+7
    int rowBase = blockIdx.x * 64;

    float acc[4][8];
    #pragma unroll
    for (int r = 0; r < 4; r++)
        #pragma unroll
        for (int c = 0; c < 8; c++) acc[r][c] = 0.0f;

    for (int kt = 0; kt < DD; kt += 32) {
        // stage A tile 64x32 (512 float4, 2 per thread)
        #pragma unroll
        for (int it = 0; it < 2; it++) {
            int li = tid + it*256;
            int r  = li >> 3;
            int c4 = li & 7;
            int grow = rowBase + r;
            float4 v = make_float4(0.f, 0.f, 0.f, 0.f);
            if (grow < NN)
                v = *reinterpret_cast<const float4*>(A + grow*DD + kt + c4*4);
            sA[r][c4*4+0] = v.x; sA[r][c4*4+1] = v.y;
            sA[r][c4*4+2] = v.z; sA[r][c4*4+3] = v.w;
        }
        // stage W tile 32x128 (1024 float4, 4 per thread)
        #pragma unroll
        for (int it = 0; it < 4; it++) {
            int li = tid + it*256;
            int r  = li >> 5;
            int c4 = li & 31;
            float4 v = *reinterpret_cast<const float4*>(W + (kt + r)*DD + c4*4);
            *reinterpret_cast<float4*>(&sW[r][c4*4]) = v;
        }
        __syncthreads();

        #pragma unroll
        for (int k = 0; k < 32; k++) {
            float av[4];
            #pragma unroll
            for (int r = 0; r < 4; r++) av[r] = sA[tr*4 + r][k];
            float4 w0 = *reinterpret_cast<const float4*>(&sW[k][tc*8]);
            float4 w1 = *reinterpret_cast<const float4*>(&sW[k][tc*8 + 4]);
            float wv[8] = {w0.x, w0.y, w0.z, w0.w, w1.x, w1.y, w1.z, w1.w};
            #pragma unroll
            for (int r = 0; r < 4; r++)
                #pragma unroll
                for (int c = 0; c < 8; c++)
                    acc[r][c] = fmaf(av[r], wv[c], acc[r][c]);
        }
        __syncthreads();
    }

    float bv[8];
    #pragma unroll
    for (int c = 0; c < 8; c++) bv[c] = bias[tc*8 + c];
    #pragma unroll
    for (int r = 0; r < 4; r++) {
        int grow = rowBase + tr*4 + r;
        if (grow < NN) {
            float4 o0, o1;
            o0.x = fmaxf(acc[r][0] + bv[0], 0.f);
            o0.y = fmaxf(acc[r][1] + bv[1], 0.f);
            o0.z = fmaxf(acc[r][2] + bv[2], 0.f);
            o0.w = fmaxf(acc[r][3] + bv[3], 0.f);
            o1.x = fmaxf(acc[r][4] + bv[4], 0.f);
            o1.y = fmaxf(acc[r][5] + bv[5], 0.f);
            o1.z = fmaxf(acc[r][6] + bv[6], 0.f);
            o1.w = fmaxf(acc[r][7] + bv[7], 0.f);
            *reinterpret_cast<float4*>(out + grow*DD + tc*8)     = o0;
            *reinterpret_cast<float4*>(out + grow*DD + tc*8 + 4) = o1;
        }
    }
}

// ---------------- output: zero, then scatter dense rows + mask ----------------
__global__ void k_zero_out(float* __restrict__ out, int n)
{
    int i = blockIdx.x * blockDim.x + threadIdx.x;
    if (i < n) out[i] = 0.0f;
}

__global__ void k_out(const int* __restrict__ batch, float* __restrict__ out, int out_size)
{
    int w = (blockIdx.x * blockDim.x + threadIdx.x) >> 5;
    if (w >= NN) return;
    int lane = threadIdx.x & 31;
    int b    = batch[w];
    int idx  = b*MAXA + (w - g_ptr[b]);
    float4 v = reinterpret_cast<const float4*>(g_x)[w*32 + lane];
    reinterpret_cast<float4*>(out)[idx*32 + lane] = v;
    if (lane == 0 && out_size >= DENSE + BBATCH*MAXA)
        out[DENSE + idx] = 1.0f;   // mask True
}

// ---------------- launch ----------------
extern "C" void kernel_launch(void* const* d_in, const int* in_sizes, int n_in,
                              void* d_out, int out_size)
{
    const float* atoms = (const float*)d_in[0];
    const int*   conn  = (const int*)d_in[1];
    const int*   batch = (const int*)d_in[2];
    const float* W_exp = (const float*)d_in[3];
    const float* b_exp = (const float*)d_in[4];
    const float* Ws    = (const float*)d_in[5];
    const float* bs    = (const float*)d_in[6];
    float* out = (float*)d_out;

    float *px, *pagg;
    cudaGetSymbolAddress((void**)&px,   g_x);
    cudaGetSymbolAddress((void**)&pagg, g_agg);

    k_zero<<<(NN + 255)/256, 256>>>();
    k_hist<<<(EE + 255)/256, 256>>>(conn + EE, batch);
    k_dinv<<<(NN + 255)/256, 256>>>();
    k_scan1<<<SCAN_NB, SCAN_BS>>>();
    k_scan2<<<1, 512>>>();
    k_scan3<<<SCAN_NB, SCAN_BS>>>();
    k_csr<<<(EE + 255)/256, 256>>>(conn);
    k_expand<<<4096, DD>>>(atoms, W_exp, b_exp);

    int aggBlocks  = (NN*32 + 255)/256;
    int gemmBlocks = (NN + 63)/64;
    for (int l = 0; l < NLAYERS; l++) {
        k_agg<<<aggBlocks, 256>>>(px, pagg);
        k_gemm<<<gemmBlocks, 256>>>(pagg, Ws + l*DD*DD, bs + l*DD, px);
    }

    k_zero_out<<<(out_size + 255)/256, 256>>>(out, out_size);
    k_out<<<aggBlocks, 256>>>(batch, out, out_size);
}

// round 4
// speedup vs baseline: 1.3747x; 1.2492x over previous
#include <cuda_runtime.h>
#include <cuda_bf16.h>
#include <cstdint>

#define NN   50000
#define EE   600000
#define FEAT 11
#define DD   128
#define BBATCH 500
#define MAXA 100
#define NLAYERS 5
#define DENSE (BBATCH*MAXA*DD)   /* 6,400,000 */

#define SCAN_BS   1024
#define SCAN_NB   ((NN + SCAN_BS - 1) / SCAN_BS)   /* 49 */

#define TILE_M    128
#define GEMM_NB   ((NN + TILE_M - 1) / TILE_M)     /* 391 */
#define NNP       (GEMM_NB * TILE_M)               /* 50048, padded */

// -------- scratch (static device globals; zero-initialized, no runtime alloc) --------
__device__ float g_x[NN*DD];              // fp32 ping (25.6 MB)
__device__ __nv_bfloat16 g_ahi[NNP*DD];   // agg result, bf16 hi (pad rows stay 0 forever)
__device__ __nv_bfloat16 g_alo[NNP*DD];   // agg result, bf16 lo
__device__ __nv_bfloat16 g_wthi[NLAYERS*DD*DD]; // W transposed [l][n][k], bf16 hi
__device__ __nv_bfloat16 g_wtlo[NLAYERS*DD*DD]; // bf16 lo
__device__ float g_dinv[NN];
__device__ float g_self[NN];
__device__ int   g_deg[NN];
__device__ int   g_rowstart[NN+1];
__device__ int   g_cursor[NN];
__device__ int   g_csr_src[EE];
__device__ float g_csr_w[EE];
__device__ int   g_counts[BBATCH];
__device__ int   g_ptr[BBATCH];
__device__ int   g_bsum[SCAN_NB];
__device__ int   g_boff[SCAN_NB];

// ---------------- graph preprocessing ----------------
__global__ void k_zero()
{
    int i = blockIdx.x * blockDim.x + threadIdx.x;
    if (i < NN) g_deg[i] = 0;
    if (i < BBATCH) g_counts[i] = 0;
}

__global__ void k_hist(const int* __restrict__ col, const int* __restrict__ batch)
{
    int i = blockIdx.x * blockDim.x + threadIdx.x;
    if (i < EE) atomicAdd(&g_deg[col[i]], 1);
    if (i < NN) atomicAdd(&g_counts[batch[i]], 1);
}

__global__ void k_dinv()
{
    int i = blockIdx.x * blockDim.x + threadIdx.x;
    if (i >= NN) return;
    float d  = (float)g_deg[i] + 2.0f;
    float di = rsqrtf(d);
    g_dinv[i] = di;
    g_self[i] = 2.0f * di * di;
}

__global__ __launch_bounds__(SCAN_BS)
void k_scan1()
{
    __shared__ int warp_sums[32];
    int tid  = threadIdx.x;
    int lane = tid & 31;
    int wid  = tid >> 5;
    int i    = blockIdx.x * SCAN_BS + tid;

    int v0 = (i < NN) ? g_deg[i] : 0;
    int v  = v0;
    #pragma unroll
    for (int off = 1; off < 32; off <<= 1) {
        int t = __shfl_up_sync(0xffffffffu, v, off);
        if (lane >= off) v += t;
    }
    if (lane == 31) warp_sums[wid] = v;
    __syncthreads();
    if (wid == 0) {
        int s = warp_sums[lane];
        #pragma unroll
        for (int off = 1; off < 32; off <<= 1) {
            int t = __shfl_up_sync(0xffffffffu, s, off);
            if (lane >= off) s += t;
        }
        warp_sums[lane] = s;
    }
    __syncthreads();
    int incl = v + (wid ? warp_sums[wid-1] : 0);
    if (i < NN) {
        g_rowstart[i+1] = incl;
        g_cursor[i]     = incl - v0;
    }
    if (tid == SCAN_BS - 1) g_bsum[blockIdx.x] = incl;
}

__global__ __launch_bounds__(512)
void k_scan2()
{
    __shared__ int sb[64];
    __shared__ int warp_sums[16];
    int tid  = threadIdx.x;
    int lane = tid & 31;
    int wid  = tid >> 5;

    if (tid < 64) sb[tid] = (tid < SCAN_NB) ? g_bsum[tid] : 0;
    __syncthreads();
    #pragma unroll
    for (int off = 1; off < 64; off <<= 1) {
        int t = 0;
        if (tid < 64 && tid >= off) t = sb[tid - off];
        __syncthreads();
        if (tid < 64) sb[tid] += t;
        __syncthreads();
    }
    if (tid < SCAN_NB) g_boff[tid] = (tid == 0) ? 0 : sb[tid - 1];
    if (tid == 0) g_rowstart[0] = 0;

    int c = (tid < BBATCH) ? g_counts[tid] : 0;
    int v = c;
    #pragma unroll
    for (int off = 1; off < 32; off <<= 1) {
        int t = __shfl_up_sync(0xffffffffu, v, off);
        if (lane >= off) v += t;
    }
    if (lane == 31) warp_sums[wid] = v;
    __syncthreads();
    if (wid == 0 && lane < 16) {
        int s = warp_sums[lane];
        #pragma unroll
        for (int off = 1; off < 16; off <<= 1) {
            int t = __shfl_up_sync(0xffffu, s, off);
            if (lane >= off) s += t;
        }
        warp_sums[lane] = s;
    }
    __syncthreads();
    int incl = v + (wid ? warp_sums[wid-1] : 0);
    if (tid < BBATCH) g_ptr[tid] = incl - c;
}

__global__ __launch_bounds__(SCAN_BS)
void k_scan3()
{
    int i = blockIdx.x * SCAN_BS + threadIdx.x;
    if (i >= NN) return;
    int off = g_boff[blockIdx.x];
    g_rowstart[i+1] += off;
    g_cursor[i]     += off;
}

__global__ void k_csr(const int* __restrict__ conn)
{
    int e = blockIdx.x * blockDim.x + threadIdx.x;
    if (e >= EE) return;
    int r = conn[e];
    int c = conn[EE + e];
    int slot = atomicAdd(&g_cursor[c], 1);
    g_csr_src[slot] = r;
    g_csr_w[slot]   = g_dinv[r] * g_dinv[c];
}

// ---- transpose W to [l][n][k] and split into bf16 hi/lo ----
__global__ void k_prepw(const float* __restrict__ Ws)
{
    int idx = blockIdx.x * blockDim.x + threadIdx.x;
    if (idx >= NLAYERS*DD*DD) return;
    int l = idx >> 14;
    int r = idx & 16383;
    int n = r >> 7;
    int k = r & 127;
    float v = Ws[l*DD*DD + k*DD + n];
    __nv_bfloat16 hi = __float2bfloat16_rn(v);
    __nv_bfloat16 lo = __float2bfloat16_rn(v - __bfloat162float(hi));
    g_wthi[idx] = hi;
    g_wtlo[idx] = lo;
}

// ---------------- log-expansion: x0 = log(atoms+1) @ W_exp + b_exp ----------------
__global__ void k_expand(const float* __restrict__ atoms,
                         const float* __restrict__ Wexp,
                         const float* __restrict__ bexp)
{
    __shared__ float sW[FEAT*DD];
    __shared__ float sb[DD];
    __shared__ float la[FEAT];
    int tid = threadIdx.x;
    for (int i = tid; i < FEAT*DD; i += DD) sW[i] = Wexp[i];
    sb[tid] = bexp[tid];
    for (int n = blockIdx.x; n < NN; n += gridDim.x) {
        __syncthreads();
        if (tid < FEAT) la[tid] = logf(atoms[n*FEAT + tid] + 1.0f);
        __syncthreads();
        float acc = sb[tid];
        #pragma unroll
        for (int f = 0; f < FEAT; f++) acc = fmaf(la[f], sW[f*DD + tid], acc);
        g_x[n*DD + tid] = acc;
    }
}

// ---------------- per-layer aggregation: agg = Â x, emitted as bf16 hi/lo ----------------
__global__ void k_agg(const float* __restrict__ x)
{
    int w = (blockIdx.x * blockDim.x + threadIdx.x) >> 5;
    if (w >= NN) return;
    int lane = threadIdx.x & 31;
    const float4* xr = reinterpret_cast<const float4*>(x);

    float4 a  = xr[w*32 + lane];
    float  sn = g_self[w];
    float4 acc = make_float4(a.x*sn, a.y*sn, a.z*sn, a.w*sn);

    int s = g_rowstart[w];
    int e = g_rowstart[w+1];
    int j = s;
    for (; j + 4 <= e; j += 4) {
        int   s0 = g_csr_src[j],   s1 = g_csr_src[j+1];
        int   s2 = g_csr_src[j+2], s3 = g_csr_src[j+3];
        float w0 = g_csr_w[j],     w1 = g_csr_w[j+1];
        float w2 = g_csr_w[j+2],   w3 = g_csr_w[j+3];
        float4 u0 = xr[s0*32 + lane];
        float4 u1 = xr[s1*32 + lane];
        float4 u2 = xr[s2*32 + lane];
        float4 u3 = xr[s3*32 + lane];
        acc.x = fmaf(u0.x, w0, acc.x); acc.y = fmaf(u0.y, w0, acc.y);
        acc.z = fmaf(u0.z, w0, acc.z); acc.w = fmaf(u0.w, w0, acc.w);
        acc.x = fmaf(u1.x, w1, acc.x); acc.y = fmaf(u1.y, w1, acc.y);
        acc.z = fmaf(u1.z, w1, acc.z); acc.w = fmaf(u1.w, w1, acc.w);
        acc.x = fmaf(u2.x, w2, acc.x); acc.y = fmaf(u2.y, w2, acc.y);
        acc.z = fmaf(u2.z, w2, acc.z); acc.w = fmaf(u2.w, w2, acc.w);
        acc.x = fmaf(u3.x, w3, acc.x); acc.y = fmaf(u3.y, w3, acc.y);
        acc.z = fmaf(u3.z, w3, acc.z); acc.w = fmaf(u3.w, w3, acc.w);
    }
    for (; j < e; j++) {
        int   src = g_csr_src[j];
        float wt  = g_csr_w[j];
        float4 u  = xr[src*32 + lane];
        acc.x = fmaf(u.x, wt, acc.x);
        acc.y = fmaf(u.y, wt, acc.y);
        acc.z = fmaf(u.z, wt, acc.z);
        acc.w = fmaf(u.w, wt, acc.w);
    }

    float vv[4] = {acc.x, acc.y, acc.z, acc.w};
    __nv_bfloat16 hi[4], lo[4];
    #pragma unroll
    for (int q = 0; q < 4; q++) {
        hi[q] = __float2bfloat16_rn(vv[q]);
        lo[q] = __float2bfloat16_rn(vv[q] - __bfloat162float(hi[q]));
    }
    uint2 phi, plo;
    phi.x = ((uint32_t)__bfloat16_as_ushort(hi[1]) << 16) | __bfloat16_as_ushort(hi[0]);
    phi.y = ((uint32_t)__bfloat16_as_ushort(hi[3]) << 16) | __bfloat16_as_ushort(hi[2]);
    plo.x = ((uint32_t)__bfloat16_as_ushort(lo[1]) << 16) | __bfloat16_as_ushort(lo[0]);
    plo.y = ((uint32_t)__bfloat16_as_ushort(lo[3]) << 16) | __bfloat16_as_ushort(lo[2]);
    reinterpret_cast<uint2*>(g_ahi)[w*32 + lane] = phi;
    reinterpret_cast<uint2*>(g_alo)[w*32 + lane] = plo;
}

// ---------------- bf16 mma.sync GEMM: out = relu((Ahi+Alo)(Whi+Wlo)^T + b) ----------------
// 3-term split; A [NNP][128] bf16 row-major, Wt [n][k] bf16 (B col-major for mma).
// CTA: 256 thr = 8 warps (4 warp_m x 2 warp_n). Warp tile: 32(M) x 64(N).
// Fragments loaded straight from global (L1/L2-resident) as 4B words.
__device__ __forceinline__ void mma_bf16(float* d, const uint32_t* a, const uint32_t* b)
{
    asm volatile(
        "mma.sync.aligned.m16n8k16.row.col.f32.bf16.bf16.f32 "
        "{%0,%1,%2,%3}, {%4,%5,%6,%7}, {%8,%9}, {%0,%1,%2,%3};"
        : "+f"(d[0]), "+f"(d[1]), "+f"(d[2]), "+f"(d[3])
        : "r"(a[0]), "r"(a[1]), "r"(a[2]), "r"(a[3]), "r"(b[0]), "r"(b[1]));
}

__global__ __launch_bounds__(256)
void k_gemm_mma(const __nv_bfloat16* __restrict__ ahi,
                const __nv_bfloat16* __restrict__ alo,
                const __nv_bfloat16* __restrict__ whi,
                const __nv_bfloat16* __restrict__ wlo,
                const float* __restrict__ bias,
                float* __restrict__ out)
{
    int tid    = threadIdx.x;
    int lane   = tid & 31;
    int wid    = tid >> 5;
    int warp_m = wid & 3;        // 0..3
    int warp_n = wid >> 2;       // 0..1
    int g      = lane >> 2;      // groupID 0..7
    int tq     = lane & 3;       // quad lane 0..3

    int rowBase = blockIdx.x * TILE_M + warp_m * 32;   // < NNP always
    int colBase = warp_n * 64;

    // row pointers (32-bit word granularity; 64 words per row of 128 bf16)
    const uint32_t* AH = reinterpret_cast<const uint32_t*>(ahi);
    const uint32_t* AL = reinterpret_cast<const uint32_t*>(alo);
    const uint32_t* BH = reinterpret_cast<const uint32_t*>(whi);
    const uint32_t* BL = reinterpret_cast<const uint32_t*>(wlo);

    const uint32_t* ah0 = AH + (rowBase + g     ) * 64;
    const uint32_t* ah1 = AH + (rowBase + g +  8) * 64;
    const uint32_t* ah2 = AH + (rowBase + g + 16) * 64;
    const uint32_t* ah3 = AH + (rowBase + g + 24) * 64;
    const uint32_t* al0 = AL + (rowBase + g     ) * 64;
    const uint32_t* al1 = AL + (rowBase + g +  8) * 64;
    const uint32_t* al2 = AL + (rowBase + g + 16) * 64;
    const uint32_t* al3 = AL + (rowBase + g + 24) * 64;
    const uint32_t* bh  = BH + (colBase + g) * 64;     // + nt*8*64
    const uint32_t* bl  = BL + (colBase + g) * 64;

    float d[2][8][4];
    #pragma unroll
    for (int mt = 0; mt < 2; mt++)
        #pragma unroll
        for (int nt = 0; nt < 8; nt++)
            #pragma unroll
            for (int q = 0; q < 4; q++) d[mt][nt][q] = 0.0f;

    #pragma unroll 4
    for (int ks = 0; ks < 8; ks++) {
        int o0 = ks*8 + tq;       // word offset for k = ks*16 + tq*2
        int o1 = o0 + 4;          // +8 bf16

        uint32_t aH[2][4], aL[2][4];
        aH[0][0] = ah0[o0]; aH[0][1] = ah1[o0]; aH[0][2] = ah0[o1]; aH[0][3] = ah1[o1];
        aH[1][0] = ah2[o0]; aH[1][1] = ah3[o0]; aH[1][2] = ah2[o1]; aH[1][3] = ah3[o1];
        aL[0][0] = al0[o0]; aL[0][1] = al1[o0]; aL[0][2] = al0[o1]; aL[0][3] = al1[o1];
        aL[1][0] = al2[o0]; aL[1][1] = al3[o0]; aL[1][2] = al2[o1]; aL[1][3] = al3[o1];

        uint32_t bHf[8][2];
        #pragma unroll
        for (int nt = 0; nt < 8; nt++) {
            bHf[nt][0] = bh[nt*512 + o0];
            bHf[nt][1] = bh[nt*512 + o1];
        }
        // hi*Whi and lo*Whi
        #pragma unroll
        for (int mt = 0; mt < 2; mt++)
            #pragma unroll
            for (int nt = 0; nt < 8; nt++)
                mma_bf16(d[mt][nt], aH[mt], bHf[nt]);
        #pragma unroll
        for (int mt = 0; mt < 2; mt++)
            #pragma unroll
            for (int nt = 0; nt < 8; nt++)
                mma_bf16(d[mt][nt], aL[mt], bHf[nt]);

        uint32_t bLf[8][2];
        #pragma unroll
        for (int nt = 0; nt < 8; nt++) {
            bLf[nt][0] = bl[nt*512 + o0];
            bLf[nt][1] = bl[nt*512 + o1];
        }
        // hi*Wlo
        #pragma unroll
        for (int mt = 0; mt < 2; mt++)
            #pragma unroll
            for (int nt = 0; nt < 8; nt++)
                mma_bf16(d[mt][nt], aH[mt], bLf[nt]);
    }

    // epilogue: bias + relu, write fp32
    #pragma unroll
    for (int nt = 0; nt < 8; nt++) {
        int cn = colBase + nt*8 + tq*2;
        float2 bv = *reinterpret_cast<const float2*>(bias + cn);
        #pragma unroll
        for (int mt = 0; mt < 2; mt++) {
            int r0 = rowBase + mt*16 + g;
            if (r0 < NN) {
                float2 o;
                o.x = fmaxf(d[mt][nt][0] + bv.x, 0.f);
                o.y = fmaxf(d[mt][nt][1] + bv.y, 0.f);
                *reinterpret_cast<float2*>(out + r0*DD + cn) = o;
            }
            int r1 = r0 + 8;
            if (r1 < NN) {
                float2 o;
                o.x = fmaxf(d[mt][nt][2] + bv.x, 0.f);
                o.y = fmaxf(d[mt][nt][3] + bv.y, 0.f);
                *reinterpret_cast<float2*>(out + r1*DD + cn) = o;
            }
        }
    }
}

// ---------------- output: zero, then scatter dense rows + mask ----------------
__global__ void k_zero_out(float* __restrict__ out, int n)
{
    int i = blockIdx.x * blockDim.x + threadIdx.x;
    if (i < n) out[i] = 0.0f;
}

__global__ void k_out(const int* __restrict__ batch, float* __restrict__ out, int out_size)
{
    int w = (blockIdx.x * blockDim.x + threadIdx.x) >> 5;
    if (w >= NN) return;
    int lane = threadIdx.x & 31;
    int b    = batch[w];
    int idx  = b*MAXA + (w - g_ptr[b]);
    float4 v = reinterpret_cast<const float4*>(g_x)[w*32 + lane];
    reinterpret_cast<float4*>(out)[idx*32 + lane] = v;
    if (lane == 0 && out_size >= DENSE + BBATCH*MAXA)
        out[DENSE + idx] = 1.0f;
}

// ---------------- launch ----------------
extern "C" void kernel_launch(void* const* d_in, const int* in_sizes, int n_in,
                              void* d_out, int out_size)
{
    const float* atoms = (const float*)d_in[0];
    const int*   conn  = (const int*)d_in[1];
    const int*   batch = (const int*)d_in[2];
    const float* W_exp = (const float*)d_in[3];
    const float* b_exp = (const float*)d_in[4];
    const float* Ws    = (const float*)d_in[5];
    const float* bs    = (const float*)d_in[6];
    float* out = (float*)d_out;

    float *px;
    __nv_bfloat16 *pahi, *palo, *pwhi, *pwlo;
    cudaGetSymbolAddress((void**)&px,   g_x);
    cudaGetSymbolAddress((void**)&pahi, g_ahi);
    cudaGetSymbolAddress((void**)&palo, g_alo);
    cudaGetSymbolAddress((void**)&pwhi, g_wthi);
    cudaGetSymbolAddress((void**)&pwlo, g_wtlo);

    k_zero<<<(NN + 255)/256, 256>>>();
    k_hist<<<(EE + 255)/256, 256>>>(conn + EE, batch);
    k_dinv<<<(NN + 255)/256, 256>>>();
    k_scan1<<<SCAN_NB, SCAN_BS>>>();
    k_scan2<<<1, 512>>>();
    k_scan3<<<SCAN_NB, SCAN_BS>>>();
    k_csr<<<(EE + 255)/256, 256>>>(conn);
    k_prepw<<<(NLAYERS*DD*DD + 255)/256, 256>>>(Ws);
    k_expand<<<4096, DD>>>(atoms, W_exp, b_exp);

    int aggBlocks = (NN*32 + 255)/256;
    for (int l = 0; l < NLAYERS; l++) {
        k_agg<<<aggBlocks, 256>>>(px);
        k_gemm_mma<<<GEMM_NB, 256>>>(pahi, palo, pwhi + l*DD*DD, pwlo + l*DD*DD,
                                     bs + l*DD, px);
    }

    k_zero_out<<<(out_size + 255)/256, 256>>>(out, out_size);
    k_out<<<aggBlocks, 256>>>(batch, out, out_size);
}